// round 17
// baseline (speedup 1.0000x reference)
#include <cuda_runtime.h>
#include <cuda_fp16.h>
#include <cstdint>

// B=4, N=4096, D=256
// scores = (V V^T)/16 ; edges = softsign(scores)
// dstate = edges @ state ; dval = edges @ val
// Pure-fp16 HMMA flash kernel, persistent A-fragments, BJ=64 (half the
// barriers), phase B 64x64 warp tiles. One-barrier pipeline: pass h =
// phase B(h-1) + phase A(h). Vj triple-buffered, E double-buffered.

#define BATCH 4
#define NN 4096
#define DD 256
#define BM 128
#define BJ 64
#define NIT (NN / BJ)     // 64
#define THREADS 256
#define ROWB 528          // fp16 V-tile row pitch (conflict-free ldsm)
#define EP 144            // E row pitch for 64 cols (9 chunks, conflict-free)
#define VJS 33792u        // one Vj stage: 64 rows fp16
#define ESZ 18432u        // one E stage: 128 * 144

static constexpr uint32_t S_VI  = 0;                      // 128*528 = 67584
static constexpr uint32_t S_VJ  = 67584;                  // 3 stages = 101376
static constexpr uint32_t S_E   = 168960;                 // 2 x 18432 = 36864
static constexpr uint32_t S_ST  = 205824;                 // 3 x 256B
static constexpr uint32_t SMEM_BYTES = 206848;

__device__ __half g_vhi[(size_t)BATCH * NN * DD];

__device__ __forceinline__ uint32_t smem_u32(const void* p) {
    uint32_t a;
    asm("{ .reg .u64 t; cvta.to.shared.u64 t, %1; cvt.u32.u64 %0, t; }" : "=r"(a) : "l"(p));
    return a;
}
__device__ __forceinline__ void cpa16(uint32_t dst, const void* src) {
    asm volatile("cp.async.cg.shared.global [%0], [%1], 16;" :: "r"(dst), "l"(src) : "memory");
}
#define CP_COMMIT()   asm volatile("cp.async.commit_group;" ::: "memory")
#define CP_WAIT_ALL() asm volatile("cp.async.wait_group 0;" ::: "memory")

__device__ __forceinline__ void ldm_x4(uint32_t* r, uint32_t addr) {
    asm volatile("ldmatrix.sync.aligned.m8n8.x4.shared.b16 {%0,%1,%2,%3}, [%4];"
        : "=r"(r[0]), "=r"(r[1]), "=r"(r[2]), "=r"(r[3]) : "r"(addr));
}
__device__ __forceinline__ void ldm_x4_t(uint32_t* r, uint32_t addr) {
    asm volatile("ldmatrix.sync.aligned.m8n8.x4.trans.shared.b16 {%0,%1,%2,%3}, [%4];"
        : "=r"(r[0]), "=r"(r[1]), "=r"(r[2]), "=r"(r[3]) : "r"(addr));
}
__device__ __forceinline__ void mma16816(float* c, const uint32_t* a, const uint32_t* b) {
    asm volatile("mma.sync.aligned.m16n8k16.row.col.f32.f16.f16.f32 "
        "{%0,%1,%2,%3}, {%4,%5,%6,%7}, {%8,%9}, {%0,%1,%2,%3};"
        : "+f"(c[0]), "+f"(c[1]), "+f"(c[2]), "+f"(c[3])
        : "r"(a[0]), "r"(a[1]), "r"(a[2]), "r"(a[3]), "r"(b[0]), "r"(b[1]));
}
__device__ __forceinline__ uint32_t h2pk(float x, float y) {
    __half2 t = __floats2half2_rn(x, y);
    return *reinterpret_cast<uint32_t*>(&t);
}

__global__ __launch_bounds__(256) void split_kernel(const float* __restrict__ val) {
    const int b = blockIdx.y, n0 = blockIdx.x * 64;
    const size_t base = ((size_t)b * NN + n0) * DD;
    #pragma unroll
    for (int k = 0; k < 16; k++) {
        int u = threadIdx.x + 256 * k;
        float4 v = *(const float4*)(val + base + (size_t)u * 4);
        *(uint2*)(g_vhi + base + (size_t)u * 4) = make_uint2(h2pk(v.x, v.y), h2pk(v.z, v.w));
    }
}

__global__ __launch_bounds__(THREADS, 1)
void prop_hmma(const float* __restrict__ state,
               float* __restrict__ dstate, float* __restrict__ dval)
{
    extern __shared__ char smem[];
    const uint32_t sb = smem_u32(smem);
    const int tid = threadIdx.x, l = tid & 31, wid = tid >> 5;
    const int r2 = wid & 1, c4 = wid >> 1;     // phase B: 64-row block, 64-col block
    const int b = blockIdx.y, i0 = blockIdx.x * BM;
    const size_t vbase = (size_t)b * NN * DD;
    const float* stateb = state + (size_t)b * NN;

    // ---- prologue: Vi fill + stage 0 ----
    {
        #pragma unroll
        for (int k = 0; k < 16; k++) {            // Vi: 4096 chunks
            int u = tid + 256 * k;
            int row = u >> 5, ch = u & 31;
            cpa16(sb + S_VI + (uint32_t)(row * ROWB + ch * 16),
                  g_vhi + vbase + (size_t)(i0 + row) * DD + ch * 8);
        }
        #pragma unroll
        for (int k = 0; k < 8; k++) {             // stage 0: 2048 chunks (64 rows)
            int u = tid + 256 * k;
            int row = u >> 5, ch = u & 31;
            cpa16(sb + S_VJ + (uint32_t)(row * ROWB + ch * 16),
                  g_vhi + vbase + (size_t)row * DD + ch * 8);
        }
        if (tid < 16) cpa16(sb + S_ST + tid * 16, stateb + tid * 4);
        CP_COMMIT();
    }

    const uint32_t offA  = (uint32_t)((l & 15) * ROWB + (l >> 4) * 16);
    const uint32_t offAE = (uint32_t)((l & 15) * EP + (l >> 4) * 16);
    const uint32_t offBn = (uint32_t)(((l & 7) + ((l & 16) ? 8 : 0)) * ROWB + ((l >> 3) & 1) * 16);

    // ---- wait prologue, hoist persistent A fragments (16 rows per warp) ----
    uint32_t ap[16][4];
    {
        CP_WAIT_ALL();
        __syncthreads();
        const uint32_t viA = sb + S_VI + (uint32_t)(wid * 16 * ROWB) + offA;
        #pragma unroll
        for (int s = 0; s < 16; s++) ldm_x4(ap[s], viA + s * 32);
    }

    float dacc[4][8][4];    // phase B: 64 rows x 64-col slice
    #pragma unroll
    for (int mt = 0; mt < 4; mt++)
        #pragma unroll
        for (int n8 = 0; n8 < 8; n8++)
            dacc[mt][n8][0] = dacc[mt][n8][1] = dacc[mt][n8][2] = dacc[mt][n8][3] = 0.f;
    float ds0 = 0.f, ds1 = 0.f;
    const float scale = 0.0625f;
    const int c0 = 2 * (l & 3);

    int cur3 = 0;    // h % 3

    for (int h = 0; h <= NIT; h++) {
        CP_WAIT_ALL();
        __syncthreads();

        // ---- fill(h+1) (post-barrier: clobbers stage (h-2)%3, readers done) ----
        if (h + 1 < NIT) {
            const int nx3 = (cur3 == 2) ? 0 : cur3 + 1;
            const int j0 = (h + 1) * BJ;
            uint32_t bufn = sb + S_VJ + (uint32_t)nx3 * VJS;
            #pragma unroll
            for (int k = 0; k < 8; k++) {
                int u = tid + 256 * k;
                int row = u >> 5, ch = u & 31;
                cpa16(bufn + (uint32_t)(row * ROWB + ch * 16),
                      g_vhi + vbase + (size_t)(j0 + row) * DD + ch * 8);
            }
            if (tid < 16) cpa16(sb + S_ST + (uint32_t)nx3 * 256u + tid * 16, stateb + j0 + tid * 4);
        }
        CP_COMMIT();

        // ---- Phase B(h-1): dval[64x64 tile] += E[64x64] @ Vj[64 x 64-cols] ----
        if (h >= 1) {
            const int p3 = (cur3 == 0) ? 2 : cur3 - 1;
            const uint32_t bufp = sb + S_VJ + (uint32_t)p3 * VJS;
            const uint32_t eAb  = sb + S_E + (uint32_t)((h - 1) & 1) * ESZ
                                + (uint32_t)(r2 * 64 * EP) + offAE;
            const uint32_t vjTb = bufp + offA + (uint32_t)(c4 * 128);   // col block c4*64
            #pragma unroll
            for (int kt = 0; kt < 4; kt++) {
                uint32_t bt[4][4];
                #pragma unroll
                for (int j = 0; j < 4; j++)
                    ldm_x4_t(bt[j], vjTb + kt * (16 * ROWB) + j * 32);
                #pragma unroll
                for (int mt = 0; mt < 4; mt++) {
                    uint32_t ef[4];
                    ldm_x4(ef, eAb + (uint32_t)(mt * 16 * EP) + kt * 32);
                    #pragma unroll
                    for (int j = 0; j < 4; j++) {
                        mma16816(dacc[mt][2 * j],     ef, bt[j] + 0);
                        mma16816(dacc[mt][2 * j + 1], ef, bt[j] + 2);
                    }
                }
            }
        }

        // ---- Phase A(h): two 32-j halves, S[16 x 32] each (A persistent) ----
        if (h < NIT) {
            const uint32_t bufb = sb + S_VJ + (uint32_t)cur3 * VJS;
            const float* stp = (const float*)(smem + S_ST + (uint32_t)cur3 * 256u);
            const uint32_t eW = sb + S_E + (uint32_t)(h & 1) * ESZ;

            #pragma unroll
            for (int jj = 0; jj < 2; jj++) {
                const uint32_t vjB0 = bufb + (uint32_t)(jj * 32 * ROWB) + offBn;
                const uint32_t vjB1 = vjB0 + 16 * ROWB;

                float sacc[4][4];
                #pragma unroll
                for (int t = 0; t < 4; t++)
                    { sacc[t][0] = sacc[t][1] = sacc[t][2] = sacc[t][3] = 0.f; }

                #pragma unroll
                for (int s = 0; s < 16; s++) {
                    uint32_t bh[4], bh2[4];
                    ldm_x4(bh,  vjB0 + s * 32);
                    ldm_x4(bh2, vjB1 + s * 32);
                    mma16816(sacc[0], ap[s], bh + 0);
                    mma16816(sacc[1], ap[s], bh + 2);
                    mma16816(sacc[2], ap[s], bh2 + 0);
                    mma16816(sacc[3], ap[s], bh2 + 2);
                }

                #pragma unroll
                for (int nt = 0; nt < 4; nt++) {
                    const float* sc = sacc[nt];
                    float f0 = sc[0] * scale, f1 = sc[1] * scale;
                    float f2 = sc[2] * scale, f3 = sc[3] * scale;
                    float e0 = __fdividef(f0, 1.0f + fabsf(f0));
                    float e1 = __fdividef(f1, 1.0f + fabsf(f1));
                    float e2 = __fdividef(f2, 1.0f + fabsf(f2));
                    float e3 = __fdividef(f3, 1.0f + fabsf(f3));
                    int col = jj * 32 + nt * 8 + c0;
                    float sA = stp[col], sB = stp[col + 1];
                    ds0 += e0 * sA + e1 * sB;
                    ds1 += e2 * sA + e3 * sB;
                    uint32_t ea = eW + (uint32_t)((wid * 16 + (l >> 2)) * EP + col * 2);
                    asm volatile("st.shared.b32 [%0], %1;" :: "r"(ea), "r"(h2pk(e0, e1)));
                    asm volatile("st.shared.b32 [%0], %1;" :: "r"(ea + 8 * EP), "r"(h2pk(e2, e3)));
                }
            }
        }

        cur3 = (cur3 == 2) ? 0 : cur3 + 1;
    }

    // ---- write dval (warp owns rows r2*64..+64, cols c4*64..+64) ----
    {
        float* dvb = dval + (size_t)b * NN * DD + (size_t)(i0 + r2 * 64) * DD + c4 * 64;
        #pragma unroll
        for (int mt = 0; mt < 4; mt++) {
            float* d0 = dvb + (size_t)(mt * 16 + (l >> 2)) * DD;
            float* d1 = d0 + 8 * DD;
            #pragma unroll
            for (int n8 = 0; n8 < 8; n8++) {
                int c = 8 * n8 + c0;
                *(float2*)(d0 + c) = make_float2(dacc[mt][n8][0], dacc[mt][n8][1]);
                *(float2*)(d1 + c) = make_float2(dacc[mt][n8][2], dacc[mt][n8][3]);
            }
        }
    }
    // ---- dstate: warp owns rows wid*16..+16; lane-reduce only ----
    ds0 += __shfl_xor_sync(0xFFFFFFFFu, ds0, 1);
    ds0 += __shfl_xor_sync(0xFFFFFFFFu, ds0, 2);
    ds1 += __shfl_xor_sync(0xFFFFFFFFu, ds1, 1);
    ds1 += __shfl_xor_sync(0xFFFFFFFFu, ds1, 2);
    if ((l & 3) == 0) {
        int r = i0 + wid * 16 + (l >> 2);
        dstate[(size_t)b * NN + r]     = ds0;
        dstate[(size_t)b * NN + r + 8] = ds1;
    }
}

extern "C" void kernel_launch(void* const* d_in, const int* in_sizes, int n_in,
                              void* d_out, int out_size)
{
    const float* val   = (const float*)d_in[0];   // [B, N, D]
    const float* state = (const float*)d_in[1];   // [B, N]
    float* dstate = (float*)d_out;                // [B, N]
    float* dval   = dstate + (size_t)BATCH * NN;  // [B, N, D]
    (void)in_sizes; (void)n_in; (void)out_size;

    dim3 gs(NN / 64, BATCH);
    split_kernel<<<gs, 256>>>(val);

    cudaFuncSetAttribute(prop_hmma,
                         cudaFuncAttributeMaxDynamicSharedMemorySize, (int)SMEM_BYTES);
    dim3 grid(NN / BM, BATCH);
    prop_hmma<<<grid, THREADS, SMEM_BYTES>>>(state, dstate, dval);
}